// round 1
// baseline (speedup 1.0000x reference)
#include <cuda_runtime.h>
#include <math.h>

// Problem constants
#define S_LEN   2048
#define D_MODEL 4096
#define NH      32
#define NKV     8
#define HD      128
#define QDIM    (NH * HD)     // 4096
#define KVDIM   (NKV * HD)    // 1024

// Scratch (no cudaMalloc allowed)
__device__ float g_Q[S_LEN * QDIM];
__device__ float g_K[S_LEN * KVDIM];
__device__ float g_V[S_LEN * KVDIM];
__device__ float g_O[S_LEN * QDIM];

// ---------------------------------------------------------------------------
// Tiled fp32 SGEMM: C[M,N] = A[M,K] @ B[K,N], all row-major.
// BM=128, BN=128, BK=16, 256 threads, 8x8 per thread.
// Requires M%128==0, N%128==0, K%16==0 (true for all our shapes).
// ---------------------------------------------------------------------------
__global__ __launch_bounds__(256) void sgemm_kernel(
    const float* __restrict__ A, const float* __restrict__ B,
    float* __restrict__ C, int M, int N, int K)
{
    const int BM = 128, BN = 128, BK = 16, TM = 8, TN = 8;
    __shared__ float As[BK][BM];   // A tile, transposed: As[k][m]
    __shared__ float Bs[BK][BN];   // B tile: Bs[k][n]

    int tid  = threadIdx.x;
    int bcol = blockIdx.x;   // N tile
    int brow = blockIdx.y;   // M tile

    int tcol = tid % (BN / TN);   // 0..15
    int trow = tid / (BN / TN);   // 0..15

    float acc[TM][TN];
#pragma unroll
    for (int i = 0; i < TM; i++)
#pragma unroll
        for (int j = 0; j < TN; j++) acc[i][j] = 0.0f;

    // Global load mapping
    int a_r = tid / 4;            // 0..63 (two rows: +0, +64)
    int a_c = (tid % 4) * 4;      // 0,4,8,12
    int b_r = tid / 32;           // 0..7  (two rows: +0, +8)
    int b_c = (tid % 32) * 4;     // 0..124

    const float* Ab = A + (size_t)brow * BM * K;
    const float* Bb = B + (size_t)bcol * BN;

    for (int k0 = 0; k0 < K; k0 += BK) {
#pragma unroll
        for (int i = 0; i < 2; i++) {
            int r = a_r + i * 64;
            float4 v = *(const float4*)(Ab + (size_t)r * K + k0 + a_c);
            As[a_c + 0][r] = v.x;
            As[a_c + 1][r] = v.y;
            As[a_c + 2][r] = v.z;
            As[a_c + 3][r] = v.w;
        }
#pragma unroll
        for (int i = 0; i < 2; i++) {
            int r = b_r + i * 8;
            float4 v = *(const float4*)(Bb + (size_t)(k0 + r) * N + b_c);
            *(float4*)&Bs[r][b_c] = v;
        }
        __syncthreads();

#pragma unroll
        for (int kk = 0; kk < BK; kk++) {
            float ra[TM], rb[TN];
            *(float4*)&ra[0] = *(const float4*)&As[kk][trow * TM + 0];
            *(float4*)&ra[4] = *(const float4*)&As[kk][trow * TM + 4];
            *(float4*)&rb[0] = *(const float4*)&Bs[kk][tcol * TN + 0];
            *(float4*)&rb[4] = *(const float4*)&Bs[kk][tcol * TN + 4];
#pragma unroll
            for (int i = 0; i < TM; i++)
#pragma unroll
                for (int j = 0; j < TN; j++)
                    acc[i][j] += ra[i] * rb[j];
        }
        __syncthreads();
    }

#pragma unroll
    for (int i = 0; i < TM; i++) {
        int r = brow * BM + trow * TM + i;
#pragma unroll
        for (int j = 0; j < TN; j += 4) {
            float4 v = make_float4(acc[i][j], acc[i][j + 1], acc[i][j + 2], acc[i][j + 3]);
            *(float4*)(C + (size_t)r * N + bcol * BN + tcol * TN + j) = v;
        }
    }
}

// ---------------------------------------------------------------------------
// RoPE (in place): buf is [S, heads*128]; rotate-half formulation.
// ---------------------------------------------------------------------------
__global__ void rope_kernel(float* __restrict__ buf, int heads)
{
    int idx = blockIdx.x * blockDim.x + threadIdx.x;
    int total = S_LEN * heads * 64;
    if (idx >= total) return;
    int i = idx % 64;
    int h = (idx / 64) % heads;
    int s = idx / (64 * heads);

    float inv_freq = powf(10000.0f, -(float)i / 64.0f);
    float ang = (float)s * inv_freq;
    float c = cosf(ang), sn = sinf(ang);

    size_t base = (size_t)s * heads * HD + (size_t)h * HD + i;
    float q0 = buf[base];
    float q1 = buf[base + 64];
    buf[base]      = q0 * c - q1 * sn;
    buf[base + 64] = q1 * c + q0 * sn;
}

// ---------------------------------------------------------------------------
// Flash-style causal GQA attention, fp32, online softmax.
// Grid: (S/64, NH). Block: 256 threads. BM=BN=64, HD=128.
// Thread tiling strided by 16 so all hot LDS are conflict-free/broadcast.
// ---------------------------------------------------------------------------
#define AW_Q 129   // padded width for Qs / Ks rows
#define AW_P 65    // padded width for Ps rows

__global__ __launch_bounds__(256) void attn_kernel(
    const float* __restrict__ Q, const float* __restrict__ K,
    const float* __restrict__ V, float* __restrict__ O)
{
    extern __shared__ float sm[];
    float* Qs   = sm;                       // [64][129]
    float* Ks   = Qs + 64 * AW_Q;           // [64][129]
    float* Vs   = Ks + 64 * AW_Q;           // [64][128]
    float* Ps   = Vs + 64 * HD;             // [64][65]
    float* mbuf = Ps + 64 * AW_P;           // [64]
    float* lbuf = mbuf + 64;                // [64]
    float* abuf = lbuf + 64;                // [64]

    int qb  = blockIdx.x;
    int h   = blockIdx.y;
    int kvh = h / (NH / NKV);

    int tid = threadIdx.x;
    int tc  = tid % 16;   // col group
    int tr  = tid / 16;   // row group

    // Load Q tile (rows qb*64.., cols h*128..)
#pragma unroll
    for (int rep = 0; rep < 8; rep++) {
        int idx = rep * 256 + tid;        // float4 index 0..2047
        int r = idx / 32;
        int c4 = (idx % 32) * 4;
        float4 v = *(const float4*)(Q + (size_t)(qb * 64 + r) * QDIM + h * HD + c4);
        Qs[r * AW_Q + c4 + 0] = v.x;
        Qs[r * AW_Q + c4 + 1] = v.y;
        Qs[r * AW_Q + c4 + 2] = v.z;
        Qs[r * AW_Q + c4 + 3] = v.w;
    }
    if (tid < 64) { mbuf[tid] = -1e30f; lbuf[tid] = 0.0f; }

    float Oacc[4][8];
#pragma unroll
    for (int i = 0; i < 4; i++)
#pragma unroll
        for (int j = 0; j < 8; j++) Oacc[i][j] = 0.0f;

    __syncthreads();

    const float scale = 0.08838834764831845f;  // 1/sqrt(128)
    int nkb = qb + 1;

    for (int kb = 0; kb < nkb; kb++) {
        // Load K, V tiles
#pragma unroll
        for (int rep = 0; rep < 8; rep++) {
            int idx = rep * 256 + tid;
            int r = idx / 32;
            int c4 = (idx % 32) * 4;
            size_t goff = (size_t)(kb * 64 + r) * KVDIM + kvh * HD + c4;
            float4 kv = *(const float4*)(K + goff);
            Ks[r * AW_Q + c4 + 0] = kv.x;
            Ks[r * AW_Q + c4 + 1] = kv.y;
            Ks[r * AW_Q + c4 + 2] = kv.z;
            Ks[r * AW_Q + c4 + 3] = kv.w;
            float4 vv = *(const float4*)(V + goff);
            *(float4*)&Vs[r * HD + c4] = vv;
        }
        __syncthreads();

        // S = Q @ K^T for this tile; thread owns rows tr+i*16, cols tc+j*16
        float acc[4][4];
#pragma unroll
        for (int i = 0; i < 4; i++)
#pragma unroll
            for (int j = 0; j < 4; j++) acc[i][j] = 0.0f;

        for (int kk = 0; kk < HD; kk++) {
            float a[4], b[4];
#pragma unroll
            for (int i = 0; i < 4; i++) a[i] = Qs[(tr + i * 16) * AW_Q + kk];
#pragma unroll
            for (int j = 0; j < 4; j++) b[j] = Ks[(tc + j * 16) * AW_Q + kk];
#pragma unroll
            for (int i = 0; i < 4; i++)
#pragma unroll
                for (int j = 0; j < 4; j++) acc[i][j] += a[i] * b[j];
        }

        // Scale + causal mask, write to Ps
#pragma unroll
        for (int i = 0; i < 4; i++) {
            int r = tr + i * 16;
#pragma unroll
            for (int j = 0; j < 4; j++) {
                int c = tc + j * 16;
                float s = acc[i][j] * scale;
                if (kb == qb && c > r) s = -1e30f;
                Ps[r * AW_P + c] = s;
            }
        }
        __syncthreads();

        // Online softmax per row (threads 0..63, one row each)
        if (tid < 64) {
            int r = tid;
            float mold = mbuf[r];
            float mx = mold;
            for (int c = 0; c < 64; c++) mx = fmaxf(mx, Ps[r * AW_P + c]);
            float alpha = __expf(mold - mx);
            float sum = 0.0f;
            for (int c = 0; c < 64; c++) {
                float p = __expf(Ps[r * AW_P + c] - mx);
                Ps[r * AW_P + c] = p;
                sum += p;
            }
            lbuf[r] = lbuf[r] * alpha + sum;
            mbuf[r] = mx;
            abuf[r] = alpha;
        }
        __syncthreads();

        // Rescale O and accumulate P @ V
        float al[4];
#pragma unroll
        for (int i = 0; i < 4; i++) al[i] = abuf[tr + i * 16];
#pragma unroll
        for (int i = 0; i < 4; i++)
#pragma unroll
            for (int j = 0; j < 8; j++) Oacc[i][j] *= al[i];

        for (int kk = 0; kk < 64; kk++) {
            float p[4], v[8];
#pragma unroll
            for (int i = 0; i < 4; i++) p[i] = Ps[(tr + i * 16) * AW_P + kk];
#pragma unroll
            for (int j = 0; j < 8; j++) v[j] = Vs[kk * HD + tc + j * 16];
#pragma unroll
            for (int i = 0; i < 4; i++)
#pragma unroll
                for (int j = 0; j < 8; j++) Oacc[i][j] += p[i] * v[j];
        }
        __syncthreads();   // protect Ks/Vs/Ps for next iteration
    }

    // Normalize and write out
    float li[4];
#pragma unroll
    for (int i = 0; i < 4; i++) li[i] = 1.0f / lbuf[tr + i * 16];
#pragma unroll
    for (int i = 0; i < 4; i++) {
        int r = qb * 64 + tr + i * 16;
#pragma unroll
        for (int j = 0; j < 8; j++) {
            O[(size_t)r * QDIM + h * HD + tc + j * 16] = Oacc[i][j] * li[i];
        }
    }
}

// ---------------------------------------------------------------------------
// Launch
// ---------------------------------------------------------------------------
extern "C" void kernel_launch(void* const* d_in, const int* in_sizes, int n_in,
                              void* d_out, int out_size)
{
    (void)in_sizes; (void)n_in; (void)out_size;

    const float* x  = (const float*)d_in[0];   // [2048, 4096]
    const float* wq = (const float*)d_in[1];   // [4096, 4096]
    const float* wk = (const float*)d_in[2];   // [4096, 1024]
    const float* wv = (const float*)d_in[3];   // [4096, 1024]
    const float* wo = (const float*)d_in[4];   // [4096, 4096]
    float* out = (float*)d_out;                // [2048, 4096]

    float *qp, *kp, *vp, *op;
    cudaGetSymbolAddress((void**)&qp, g_Q);
    cudaGetSymbolAddress((void**)&kp, g_K);
    cudaGetSymbolAddress((void**)&vp, g_V);
    cudaGetSymbolAddress((void**)&op, g_O);

    // QKV projections
    {
        dim3 gq(QDIM / 128, S_LEN / 128);
        sgemm_kernel<<<gq, 256>>>(x, wq, qp, S_LEN, QDIM, D_MODEL);
        dim3 gk(KVDIM / 128, S_LEN / 128);
        sgemm_kernel<<<gk, 256>>>(x, wk, kp, S_LEN, KVDIM, D_MODEL);
        sgemm_kernel<<<gk, 256>>>(x, wv, vp, S_LEN, KVDIM, D_MODEL);
    }

    // RoPE on Q and K
    {
        int tq = S_LEN * NH * 64;
        rope_kernel<<<(tq + 255) / 256, 256>>>(qp, NH);
        int tk = S_LEN * NKV * 64;
        rope_kernel<<<(tk + 255) / 256, 256>>>(kp, NKV);
    }

    // Attention
    {
        size_t smem = (size_t)(64 * AW_Q * 2 + 64 * HD + 64 * AW_P + 3 * 64) * sizeof(float);
        cudaFuncSetAttribute(attn_kernel, cudaFuncAttributeMaxDynamicSharedMemorySize, (int)smem);
        dim3 ga(S_LEN / 64, NH);
        attn_kernel<<<ga, 256, smem>>>(qp, kp, vp, op);
    }

    // Output projection
    {
        dim3 go(D_MODEL / 128, S_LEN / 128);
        sgemm_kernel<<<go, 256>>>(op, wo, out, S_LEN, D_MODEL, QDIM);
    }
}

// round 2
// speedup vs baseline: 1.9962x; 1.9962x over previous
#include <cuda_runtime.h>
#include <math.h>
#include <stdint.h>

// Problem constants
#define S_LEN   2048
#define D_MODEL 4096
#define NH      32
#define NKV     8
#define HD      128
#define QDIM    (NH * HD)     // 4096
#define KVDIM   (NKV * HD)    // 1024

// Scratch (no cudaMalloc allowed)
__device__ float g_Q[S_LEN * QDIM];
__device__ float g_K[S_LEN * KVDIM];
__device__ float g_V[S_LEN * KVDIM];
__device__ float g_O[S_LEN * QDIM];

// ---------------------------------------------------------------------------
// tf32 tensor-core GEMM: C[M,N] = A[M,K] @ B[K,N], row-major fp32 in/out.
// BM=128, BN=128, BK=32. 256 threads = 8 warps (2x4), warp tile 64x32.
// mma.sync.aligned.m16n8k8.row.col.f32.tf32.tf32.f32
// Requires M%128==0, N%128==0, K%32==0.
// ---------------------------------------------------------------------------
#define AS_STRIDE 36    // floats per A row (BK=32 + pad) -> read banks (4m+k) distinct
#define BS_STRIDE 136   // floats per B row (BN=128 + pad) -> read banks (8k+n) distinct

__device__ __forceinline__ uint32_t f2tf32(float f) {
    uint32_t r;
    asm("cvt.rna.tf32.f32 %0, %1;" : "=r"(r) : "f"(f));
    return r;
}

__global__ __launch_bounds__(256) void gemm_tf32_kernel(
    const float* __restrict__ A, const float* __restrict__ B,
    float* __restrict__ C, int M, int N, int K)
{
    __shared__ uint32_t As[128 * AS_STRIDE];
    __shared__ uint32_t Bs[32 * BS_STRIDE];

    const int tid  = threadIdx.x;
    const int wid  = tid / 32;
    const int lane = tid % 32;
    const int wm   = wid / 4;       // 0..1
    const int wn   = wid % 4;       // 0..3
    const int lg   = lane / 4;      // group id 0..7
    const int lk   = lane % 4;      // 0..3

    const int brow = blockIdx.y;
    const int bcol = blockIdx.x;

    // Global load mapping
    const int a_m0 = tid / 8;            // 0..31 (rows +0,32,64,96)
    const int a_k4 = (tid % 8) * 4;      // 0..28
    const int b_k0 = tid / 32;           // 0..7  (rows +0,8,16,24)
    const int b_n4 = (tid % 32) * 4;     // 0..124

    const float* Ab = A + (size_t)brow * 128 * K;
    const float* Bb = B + (size_t)bcol * 128;

    float acc[4][4][4];
#pragma unroll
    for (int i = 0; i < 4; i++)
#pragma unroll
        for (int j = 0; j < 4; j++)
#pragma unroll
            for (int c = 0; c < 4; c++) acc[i][j][c] = 0.0f;

    for (int k0 = 0; k0 < K; k0 += 32) {
        // Load A tile 128x32 -> As (convert to tf32)
#pragma unroll
        for (int r = 0; r < 4; r++) {
            int m = a_m0 + r * 32;
            float4 v = *(const float4*)(Ab + (size_t)m * K + k0 + a_k4);
            uint4 t;
            t.x = f2tf32(v.x); t.y = f2tf32(v.y);
            t.z = f2tf32(v.z); t.w = f2tf32(v.w);
            *(uint4*)&As[m * AS_STRIDE + a_k4] = t;
        }
        // Load B tile 32x128 -> Bs
#pragma unroll
        for (int r = 0; r < 4; r++) {
            int kk = b_k0 + r * 8;
            float4 v = *(const float4*)(Bb + (size_t)(k0 + kk) * N + b_n4);
            uint4 t;
            t.x = f2tf32(v.x); t.y = f2tf32(v.y);
            t.z = f2tf32(v.z); t.w = f2tf32(v.w);
            *(uint4*)&Bs[kk * BS_STRIDE + b_n4] = t;
        }
        __syncthreads();

#pragma unroll
        for (int ks = 0; ks < 4; ks++) {
            uint32_t af[4][4];
#pragma unroll
            for (int fm = 0; fm < 4; fm++) {
                int m = wm * 64 + fm * 16 + lg;
                int kk = ks * 8 + lk;
                af[fm][0] = As[m * AS_STRIDE + kk];
                af[fm][1] = As[(m + 8) * AS_STRIDE + kk];
                af[fm][2] = As[m * AS_STRIDE + kk + 4];
                af[fm][3] = As[(m + 8) * AS_STRIDE + kk + 4];
            }
            uint32_t bf[4][2];
#pragma unroll
            for (int fn = 0; fn < 4; fn++) {
                int n = wn * 32 + fn * 8 + lg;
                int kk = ks * 8 + lk;
                bf[fn][0] = Bs[kk * BS_STRIDE + n];
                bf[fn][1] = Bs[(kk + 4) * BS_STRIDE + n];
            }
#pragma unroll
            for (int fm = 0; fm < 4; fm++)
#pragma unroll
                for (int fn = 0; fn < 4; fn++) {
                    asm volatile(
                        "mma.sync.aligned.m16n8k8.row.col.f32.tf32.tf32.f32 "
                        "{%0,%1,%2,%3}, {%4,%5,%6,%7}, {%8,%9}, {%0,%1,%2,%3};\n"
                        : "+f"(acc[fm][fn][0]), "+f"(acc[fm][fn][1]),
                          "+f"(acc[fm][fn][2]), "+f"(acc[fm][fn][3])
                        : "r"(af[fm][0]), "r"(af[fm][1]), "r"(af[fm][2]), "r"(af[fm][3]),
                          "r"(bf[fn][0]), "r"(bf[fn][1]));
                }
        }
        __syncthreads();
    }

    // Epilogue
#pragma unroll
    for (int fm = 0; fm < 4; fm++) {
        int row0 = brow * 128 + wm * 64 + fm * 16 + lg;
#pragma unroll
        for (int fn = 0; fn < 4; fn++) {
            int col = bcol * 128 + wn * 32 + fn * 8 + lk * 2;
            *(float2*)(C + (size_t)row0 * N + col) =
                make_float2(acc[fm][fn][0], acc[fm][fn][1]);
            *(float2*)(C + (size_t)(row0 + 8) * N + col) =
                make_float2(acc[fm][fn][2], acc[fm][fn][3]);
        }
    }
}

// ---------------------------------------------------------------------------
// RoPE (in place): buf is [S, heads*128]; rotate-half formulation.
// ---------------------------------------------------------------------------
__global__ void rope_kernel(float* __restrict__ buf, int heads)
{
    int idx = blockIdx.x * blockDim.x + threadIdx.x;
    int total = S_LEN * heads * 64;
    if (idx >= total) return;
    int i = idx % 64;
    int h = (idx / 64) % heads;
    int s = idx / (64 * heads);

    float inv_freq = powf(10000.0f, -(float)i / 64.0f);
    float ang = (float)s * inv_freq;
    float c = cosf(ang), sn = sinf(ang);

    size_t base = (size_t)s * heads * HD + (size_t)h * HD + i;
    float q0 = buf[base];
    float q1 = buf[base + 64];
    buf[base]      = q0 * c - q1 * sn;
    buf[base + 64] = q1 * c + q0 * sn;
}

// ---------------------------------------------------------------------------
// Flash-style causal GQA attention, fp32, online softmax.
// Grid: (S/64, NH). Block: 256 threads. BM=BN=64, HD=128.
// ---------------------------------------------------------------------------
#define AW_Q 129   // padded width for Qs / Ks rows
#define AW_P 65    // padded width for Ps rows

__global__ __launch_bounds__(256) void attn_kernel(
    const float* __restrict__ Q, const float* __restrict__ K,
    const float* __restrict__ V, float* __restrict__ O)
{
    extern __shared__ float sm[];
    float* Qs   = sm;                       // [64][129]
    float* Ks   = Qs + 64 * AW_Q;           // [64][129]
    float* Vs   = Ks + 64 * AW_Q;           // [64][128]
    float* Ps   = Vs + 64 * HD;             // [64][65]
    float* mbuf = Ps + 64 * AW_P;           // [64]
    float* lbuf = mbuf + 64;                // [64]
    float* abuf = lbuf + 64;                // [64]

    int qb  = blockIdx.x;
    int h   = blockIdx.y;
    int kvh = h / (NH / NKV);

    int tid = threadIdx.x;
    int tc  = tid % 16;   // col group
    int tr  = tid / 16;   // row group

#pragma unroll
    for (int rep = 0; rep < 8; rep++) {
        int idx = rep * 256 + tid;
        int r = idx / 32;
        int c4 = (idx % 32) * 4;
        float4 v = *(const float4*)(Q + (size_t)(qb * 64 + r) * QDIM + h * HD + c4);
        Qs[r * AW_Q + c4 + 0] = v.x;
        Qs[r * AW_Q + c4 + 1] = v.y;
        Qs[r * AW_Q + c4 + 2] = v.z;
        Qs[r * AW_Q + c4 + 3] = v.w;
    }
    if (tid < 64) { mbuf[tid] = -1e30f; lbuf[tid] = 0.0f; }

    float Oacc[4][8];
#pragma unroll
    for (int i = 0; i < 4; i++)
#pragma unroll
        for (int j = 0; j < 8; j++) Oacc[i][j] = 0.0f;

    __syncthreads();

    const float scale = 0.08838834764831845f;  // 1/sqrt(128)
    int nkb = qb + 1;

    for (int kb = 0; kb < nkb; kb++) {
#pragma unroll
        for (int rep = 0; rep < 8; rep++) {
            int idx = rep * 256 + tid;
            int r = idx / 32;
            int c4 = (idx % 32) * 4;
            size_t goff = (size_t)(kb * 64 + r) * KVDIM + kvh * HD + c4;
            float4 kv = *(const float4*)(K + goff);
            Ks[r * AW_Q + c4 + 0] = kv.x;
            Ks[r * AW_Q + c4 + 1] = kv.y;
            Ks[r * AW_Q + c4 + 2] = kv.z;
            Ks[r * AW_Q + c4 + 3] = kv.w;
            float4 vv = *(const float4*)(V + goff);
            *(float4*)&Vs[r * HD + c4] = vv;
        }
        __syncthreads();

        float acc[4][4];
#pragma unroll
        for (int i = 0; i < 4; i++)
#pragma unroll
            for (int j = 0; j < 4; j++) acc[i][j] = 0.0f;

        for (int kk = 0; kk < HD; kk++) {
            float a[4], b[4];
#pragma unroll
            for (int i = 0; i < 4; i++) a[i] = Qs[(tr + i * 16) * AW_Q + kk];
#pragma unroll
            for (int j = 0; j < 4; j++) b[j] = Ks[(tc + j * 16) * AW_Q + kk];
#pragma unroll
            for (int i = 0; i < 4; i++)
#pragma unroll
                for (int j = 0; j < 4; j++) acc[i][j] += a[i] * b[j];
        }

#pragma unroll
        for (int i = 0; i < 4; i++) {
            int r = tr + i * 16;
#pragma unroll
            for (int j = 0; j < 4; j++) {
                int c = tc + j * 16;
                float s = acc[i][j] * scale;
                if (kb == qb && c > r) s = -1e30f;
                Ps[r * AW_P + c] = s;
            }
        }
        __syncthreads();

        if (tid < 64) {
            int r = tid;
            float mold = mbuf[r];
            float mx = mold;
            for (int c = 0; c < 64; c++) mx = fmaxf(mx, Ps[r * AW_P + c]);
            float alpha = __expf(mold - mx);
            float sum = 0.0f;
            for (int c = 0; c < 64; c++) {
                float p = __expf(Ps[r * AW_P + c] - mx);
                Ps[r * AW_P + c] = p;
                sum += p;
            }
            lbuf[r] = lbuf[r] * alpha + sum;
            mbuf[r] = mx;
            abuf[r] = alpha;
        }
        __syncthreads();

        float al[4];
#pragma unroll
        for (int i = 0; i < 4; i++) al[i] = abuf[tr + i * 16];
#pragma unroll
        for (int i = 0; i < 4; i++)
#pragma unroll
            for (int j = 0; j < 8; j++) Oacc[i][j] *= al[i];

        for (int kk = 0; kk < 64; kk++) {
            float p[4], v[8];
#pragma unroll
            for (int i = 0; i < 4; i++) p[i] = Ps[(tr + i * 16) * AW_P + kk];
#pragma unroll
            for (int j = 0; j < 8; j++) v[j] = Vs[kk * HD + tc + j * 16];
#pragma unroll
            for (int i = 0; i < 4; i++)
#pragma unroll
                for (int j = 0; j < 8; j++) Oacc[i][j] += p[i] * v[j];
        }
        __syncthreads();
    }

    float li[4];
#pragma unroll
    for (int i = 0; i < 4; i++) li[i] = 1.0f / lbuf[tr + i * 16];
#pragma unroll
    for (int i = 0; i < 4; i++) {
        int r = qb * 64 + tr + i * 16;
#pragma unroll
        for (int j = 0; j < 8; j++) {
            O[(size_t)r * QDIM + h * HD + tc + j * 16] = Oacc[i][j] * li[i];
        }
    }
}

// ---------------------------------------------------------------------------
// Launch
// ---------------------------------------------------------------------------
extern "C" void kernel_launch(void* const* d_in, const int* in_sizes, int n_in,
                              void* d_out, int out_size)
{
    (void)in_sizes; (void)n_in; (void)out_size;

    const float* x  = (const float*)d_in[0];   // [2048, 4096]
    const float* wq = (const float*)d_in[1];   // [4096, 4096]
    const float* wk = (const float*)d_in[2];   // [4096, 1024]
    const float* wv = (const float*)d_in[3];   // [4096, 1024]
    const float* wo = (const float*)d_in[4];   // [4096, 4096]
    float* out = (float*)d_out;                // [2048, 4096]

    float *qp, *kp, *vp, *op;
    cudaGetSymbolAddress((void**)&qp, g_Q);
    cudaGetSymbolAddress((void**)&kp, g_K);
    cudaGetSymbolAddress((void**)&vp, g_V);
    cudaGetSymbolAddress((void**)&op, g_O);

    // QKV projections (tf32 tensor cores)
    {
        dim3 gq(QDIM / 128, S_LEN / 128);
        gemm_tf32_kernel<<<gq, 256>>>(x, wq, qp, S_LEN, QDIM, D_MODEL);
        dim3 gk(KVDIM / 128, S_LEN / 128);
        gemm_tf32_kernel<<<gk, 256>>>(x, wk, kp, S_LEN, KVDIM, D_MODEL);
        gemm_tf32_kernel<<<gk, 256>>>(x, wv, vp, S_LEN, KVDIM, D_MODEL);
    }

    // RoPE on Q and K
    {
        int tq = S_LEN * NH * 64;
        rope_kernel<<<(tq + 255) / 256, 256>>>(qp, NH);
        int tk = S_LEN * NKV * 64;
        rope_kernel<<<(tk + 255) / 256, 256>>>(kp, NKV);
    }

    // Attention
    {
        size_t smem = (size_t)(64 * AW_Q * 2 + 64 * HD + 64 * AW_P + 3 * 64) * sizeof(float);
        cudaFuncSetAttribute(attn_kernel, cudaFuncAttributeMaxDynamicSharedMemorySize, (int)smem);
        dim3 ga(S_LEN / 64, NH);
        attn_kernel<<<ga, 256, smem>>>(qp, kp, vp, op);
    }

    // Output projection
    {
        dim3 go(D_MODEL / 128, S_LEN / 128);
        gemm_tf32_kernel<<<go, 256>>>(op, wo, out, S_LEN, D_MODEL, QDIM);
    }
}

// round 3
// speedup vs baseline: 3.2541x; 1.6301x over previous
#include <cuda_runtime.h>
#include <math.h>
#include <stdint.h>

// Problem constants
#define S_LEN   2048
#define D_MODEL 4096
#define NH      32
#define NKV     8
#define HD      128
#define QDIM    (NH * HD)     // 4096
#define KVDIM   (NKV * HD)    // 1024

// Scratch (no cudaMalloc allowed)
__device__ float g_Q[S_LEN * QDIM];
__device__ float g_K[S_LEN * KVDIM];
__device__ float g_V[S_LEN * KVDIM];
__device__ float g_O[S_LEN * QDIM];

__device__ __forceinline__ uint32_t f2tf32(float f) {
    uint32_t r;
    asm("cvt.rna.tf32.f32 %0, %1;" : "=r"(r) : "f"(f));
    return r;
}

#define MMA_TF32(ac, a0,a1,a2,a3, b0,b1)                                      \
    asm volatile(                                                             \
        "mma.sync.aligned.m16n8k8.row.col.f32.tf32.tf32.f32 "                 \
        "{%0,%1,%2,%3}, {%4,%5,%6,%7}, {%8,%9}, {%0,%1,%2,%3};\n"             \
        : "+f"((ac)[0]), "+f"((ac)[1]), "+f"((ac)[2]), "+f"((ac)[3])          \
        : "r"(a0), "r"(a1), "r"(a2), "r"(a3), "r"(b0), "r"(b1))

// ---------------------------------------------------------------------------
// tf32 tensor-core GEMM with register-prefetch double buffering.
// C[M,N] = A[M,K] @ B[K,N], row-major fp32. BM=BN=128, BK=32, 256 threads.
// ---------------------------------------------------------------------------
#define AS_STRIDE 36
#define BS_STRIDE 136

__global__ __launch_bounds__(256, 2) void gemm_tf32_kernel(
    const float* __restrict__ A, const float* __restrict__ B,
    float* __restrict__ C, int M, int N, int K)
{
    __shared__ uint32_t As[128 * AS_STRIDE];
    __shared__ uint32_t Bs[32 * BS_STRIDE];

    const int tid  = threadIdx.x;
    const int wid  = tid / 32;
    const int lane = tid % 32;
    const int wm   = wid / 4;
    const int wn   = wid % 4;
    const int lg   = lane / 4;
    const int lk   = lane % 4;

    const int brow = blockIdx.y;
    const int bcol = blockIdx.x;

    const int a_m0 = tid / 8;
    const int a_k4 = (tid % 8) * 4;
    const int b_k0 = tid / 32;
    const int b_n4 = (tid % 32) * 4;

    const float* Ab = A + (size_t)brow * 128 * K;
    const float* Bb = B + (size_t)bcol * 128;

    float acc[4][4][4];
#pragma unroll
    for (int i = 0; i < 4; i++)
#pragma unroll
        for (int j = 0; j < 4; j++)
#pragma unroll
            for (int c = 0; c < 4; c++) acc[i][j][c] = 0.0f;

    float4 pa[4], pb[4];
    // prefetch tile 0
#pragma unroll
    for (int r = 0; r < 4; r++)
        pa[r] = *(const float4*)(Ab + (size_t)(a_m0 + r * 32) * K + a_k4);
#pragma unroll
    for (int r = 0; r < 4; r++)
        pb[r] = *(const float4*)(Bb + (size_t)(b_k0 + r * 8) * N + b_n4);

    const int NT = K / 32;
    for (int kt = 0; kt < NT; kt++) {
        // store prefetched tile -> smem (tf32 convert)
#pragma unroll
        for (int r = 0; r < 4; r++) {
            int m = a_m0 + r * 32;
            uint4 t;
            t.x = f2tf32(pa[r].x); t.y = f2tf32(pa[r].y);
            t.z = f2tf32(pa[r].z); t.w = f2tf32(pa[r].w);
            *(uint4*)&As[m * AS_STRIDE + a_k4] = t;
        }
#pragma unroll
        for (int r = 0; r < 4; r++) {
            int kkr = b_k0 + r * 8;
            uint4 t;
            t.x = f2tf32(pb[r].x); t.y = f2tf32(pb[r].y);
            t.z = f2tf32(pb[r].z); t.w = f2tf32(pb[r].w);
            *(uint4*)&Bs[kkr * BS_STRIDE + b_n4] = t;
        }
        __syncthreads();

        if (kt + 1 < NT) {
            int k0 = (kt + 1) * 32;
#pragma unroll
            for (int r = 0; r < 4; r++)
                pa[r] = *(const float4*)(Ab + (size_t)(a_m0 + r * 32) * K + k0 + a_k4);
#pragma unroll
            for (int r = 0; r < 4; r++)
                pb[r] = *(const float4*)(Bb + (size_t)(k0 + b_k0 + r * 8) * N + b_n4);
        }

#pragma unroll
        for (int ks = 0; ks < 4; ks++) {
            uint32_t af[4][4];
#pragma unroll
            for (int fm = 0; fm < 4; fm++) {
                int m = wm * 64 + fm * 16 + lg;
                int kkk = ks * 8 + lk;
                af[fm][0] = As[m * AS_STRIDE + kkk];
                af[fm][1] = As[(m + 8) * AS_STRIDE + kkk];
                af[fm][2] = As[m * AS_STRIDE + kkk + 4];
                af[fm][3] = As[(m + 8) * AS_STRIDE + kkk + 4];
            }
            uint32_t bf[4][2];
#pragma unroll
            for (int fn = 0; fn < 4; fn++) {
                int n = wn * 32 + fn * 8 + lg;
                int kkk = ks * 8 + lk;
                bf[fn][0] = Bs[kkk * BS_STRIDE + n];
                bf[fn][1] = Bs[(kkk + 4) * BS_STRIDE + n];
            }
#pragma unroll
            for (int fm = 0; fm < 4; fm++)
#pragma unroll
                for (int fn = 0; fn < 4; fn++)
                    MMA_TF32(acc[fm][fn], af[fm][0], af[fm][1], af[fm][2], af[fm][3],
                             bf[fn][0], bf[fn][1]);
        }
        __syncthreads();
    }

#pragma unroll
    for (int fm = 0; fm < 4; fm++) {
        int row0 = brow * 128 + wm * 64 + fm * 16 + lg;
#pragma unroll
        for (int fn = 0; fn < 4; fn++) {
            int col = bcol * 128 + wn * 32 + fn * 8 + lk * 2;
            *(float2*)(C + (size_t)row0 * N + col) =
                make_float2(acc[fm][fn][0], acc[fm][fn][1]);
            *(float2*)(C + (size_t)(row0 + 8) * N + col) =
                make_float2(acc[fm][fn][2], acc[fm][fn][3]);
        }
    }
}

// ---------------------------------------------------------------------------
// RoPE (in place)
// ---------------------------------------------------------------------------
__global__ void rope_kernel(float* __restrict__ buf, int heads)
{
    int idx = blockIdx.x * blockDim.x + threadIdx.x;
    int total = S_LEN * heads * 64;
    if (idx >= total) return;
    int i = idx % 64;
    int h = (idx / 64) % heads;
    int s = idx / (64 * heads);

    float inv_freq = powf(10000.0f, -(float)i / 64.0f);
    float ang = (float)s * inv_freq;
    float c = cosf(ang), sn = sinf(ang);

    size_t base = (size_t)s * heads * HD + (size_t)h * HD + i;
    float q0 = buf[base];
    float q1 = buf[base + 64];
    buf[base]      = q0 * c - q1 * sn;
    buf[base + 64] = q1 * c + q0 * sn;
}

// ---------------------------------------------------------------------------
// Tensor-core flash attention (tf32 MMA), causal GQA.
// Grid: (S/128, NH), 256 threads = 8 warps; warp w owns 16 q-rows.
// BM=128 q rows, BN=64 kv per tile, HD=128.
// ---------------------------------------------------------------------------
#define QS_STR 132
#define KS_STR 132
#define VS_STR 136
#define PS_STR 68
#define ATT_SMEM_WORDS (128 * QS_STR + 64 * KS_STR + 64 * VS_STR + 128 * PS_STR)

__global__ __launch_bounds__(256, 1) void attn_mma_kernel(
    const float* __restrict__ Q, const float* __restrict__ K,
    const float* __restrict__ V, float* __restrict__ O)
{
    extern __shared__ uint32_t sm[];
    uint32_t* Qs = sm;                          // [128][132]
    uint32_t* Ks = Qs + 128 * QS_STR;           // [64][132]
    uint32_t* Vs = Ks + 64 * KS_STR;            // [64][136]
    uint32_t* Ps = Vs + 64 * VS_STR;            // [128][68]

    const int qb  = gridDim.x - 1 - blockIdx.x;   // big blocks launch first
    const int h   = blockIdx.y;
    const int kvh = h / (NH / NKV);

    const int tid  = threadIdx.x;
    const int lane = tid & 31;
    const int w    = tid >> 5;
    const int r    = lane >> 2;    // 0..7
    const int kk   = lane & 3;     // 0..3
    const int m0   = w * 16;

    const float scale = 0.08838834764831845f;  // 1/sqrt(128)

    // Load Q tile (scaled, tf32)
#pragma unroll
    for (int it = 0; it < 16; it++) {
        int idx = it * 256 + tid;
        int rr = idx >> 5, c4 = (idx & 31) * 4;
        float4 v = *(const float4*)(Q + (size_t)(qb * 128 + rr) * QDIM + h * HD + c4);
        uint4 t;
        t.x = f2tf32(v.x * scale); t.y = f2tf32(v.y * scale);
        t.z = f2tf32(v.z * scale); t.w = f2tf32(v.w * scale);
        *(uint4*)&Qs[rr * QS_STR + c4] = t;
    }

    float oacc[16][4];
#pragma unroll
    for (int i = 0; i < 16; i++)
#pragma unroll
        for (int c = 0; c < 4; c++) oacc[i][c] = 0.0f;

    float mrow0 = -1e30f, mrow1 = -1e30f, lrow0 = 0.0f, lrow1 = 0.0f;

    const int nkt = 2 * qb + 2;
    for (int kb = 0; kb < nkt; kb++) {
        __syncthreads();   // previous iteration's smem reads done (and Q load on iter 0)
        // Load K,V tiles (tf32)
#pragma unroll
        for (int it = 0; it < 8; it++) {
            int idx = it * 256 + tid;
            int rr = idx >> 5, c4 = (idx & 31) * 4;
            size_t go = (size_t)(kb * 64 + rr) * KVDIM + kvh * HD + c4;
            float4 kv4 = *(const float4*)(K + go);
            uint4 t;
            t.x = f2tf32(kv4.x); t.y = f2tf32(kv4.y);
            t.z = f2tf32(kv4.z); t.w = f2tf32(kv4.w);
            *(uint4*)&Ks[rr * KS_STR + c4] = t;
            float4 vv4 = *(const float4*)(V + go);
            uint4 u;
            u.x = f2tf32(vv4.x); u.y = f2tf32(vv4.y);
            u.z = f2tf32(vv4.z); u.w = f2tf32(vv4.w);
            *(uint4*)&Vs[rr * VS_STR + c4] = u;
        }
        __syncthreads();

        // S = Q @ K^T  (warp strip m16 x n64)
        float sacc[8][4];
#pragma unroll
        for (int i = 0; i < 8; i++)
#pragma unroll
            for (int c = 0; c < 4; c++) sacc[i][c] = 0.0f;

#pragma unroll
        for (int ks = 0; ks < 16; ks++) {
            uint32_t a0 = Qs[(m0 + r) * QS_STR + ks * 8 + kk];
            uint32_t a1 = Qs[(m0 + r + 8) * QS_STR + ks * 8 + kk];
            uint32_t a2 = Qs[(m0 + r) * QS_STR + ks * 8 + kk + 4];
            uint32_t a3 = Qs[(m0 + r + 8) * QS_STR + ks * 8 + kk + 4];
#pragma unroll
            for (int nm = 0; nm < 8; nm++) {
                uint32_t b0 = Ks[(nm * 8 + r) * KS_STR + ks * 8 + kk];
                uint32_t b1 = Ks[(nm * 8 + r) * KS_STR + ks * 8 + kk + 4];
                MMA_TF32(sacc[nm], a0, a1, a2, a3, b0, b1);
            }
        }

        // Causal mask (only needed on the last two k-tiles of this block)
        if (kb >= 2 * qb) {
            int gr0 = qb * 128 + m0 + r;
            int gr1 = gr0 + 8;
#pragma unroll
            for (int nm = 0; nm < 8; nm++) {
                int gc = kb * 64 + nm * 8 + 2 * kk;
                if (gc > gr0)     sacc[nm][0] = -1e30f;
                if (gc + 1 > gr0) sacc[nm][1] = -1e30f;
                if (gc > gr1)     sacc[nm][2] = -1e30f;
                if (gc + 1 > gr1) sacc[nm][3] = -1e30f;
            }
        }

        // Online softmax (rows are warp-local; reduce within quad)
        float tm0 = -1e30f, tm1 = -1e30f;
#pragma unroll
        for (int nm = 0; nm < 8; nm++) {
            tm0 = fmaxf(tm0, fmaxf(sacc[nm][0], sacc[nm][1]));
            tm1 = fmaxf(tm1, fmaxf(sacc[nm][2], sacc[nm][3]));
        }
        tm0 = fmaxf(tm0, __shfl_xor_sync(0xFFFFFFFF, tm0, 1));
        tm0 = fmaxf(tm0, __shfl_xor_sync(0xFFFFFFFF, tm0, 2));
        tm1 = fmaxf(tm1, __shfl_xor_sync(0xFFFFFFFF, tm1, 1));
        tm1 = fmaxf(tm1, __shfl_xor_sync(0xFFFFFFFF, tm1, 2));

        float mn0 = fmaxf(mrow0, tm0), mn1 = fmaxf(mrow1, tm1);
        float al0 = __expf(mrow0 - mn0), al1 = __expf(mrow1 - mn1);
        mrow0 = mn0; mrow1 = mn1;

        float sum0 = 0.0f, sum1 = 0.0f;
#pragma unroll
        for (int nm = 0; nm < 8; nm++) {
            float p0 = __expf(sacc[nm][0] - mn0);
            float p1 = __expf(sacc[nm][1] - mn0);
            float p2 = __expf(sacc[nm][2] - mn1);
            float p3 = __expf(sacc[nm][3] - mn1);
            sum0 += p0 + p1;
            sum1 += p2 + p3;
            uint2 u0; u0.x = f2tf32(p0); u0.y = f2tf32(p1);
            *(uint2*)&Ps[(m0 + r) * PS_STR + nm * 8 + 2 * kk] = u0;
            uint2 u1; u1.x = f2tf32(p2); u1.y = f2tf32(p3);
            *(uint2*)&Ps[(m0 + r + 8) * PS_STR + nm * 8 + 2 * kk] = u1;
        }
        sum0 += __shfl_xor_sync(0xFFFFFFFF, sum0, 1);
        sum0 += __shfl_xor_sync(0xFFFFFFFF, sum0, 2);
        sum1 += __shfl_xor_sync(0xFFFFFFFF, sum1, 1);
        sum1 += __shfl_xor_sync(0xFFFFFFFF, sum1, 2);
        lrow0 = lrow0 * al0 + sum0;
        lrow1 = lrow1 * al1 + sum1;

        // Rescale O accumulators
#pragma unroll
        for (int nm2 = 0; nm2 < 16; nm2++) {
            oacc[nm2][0] *= al0; oacc[nm2][1] *= al0;
            oacc[nm2][2] *= al1; oacc[nm2][3] *= al1;
        }
        __syncwarp();

        // O += P @ V  (warp strip m16 x n128, k=64)
#pragma unroll
        for (int ks2 = 0; ks2 < 8; ks2++) {
            uint32_t a0 = Ps[(m0 + r) * PS_STR + ks2 * 8 + kk];
            uint32_t a1 = Ps[(m0 + r + 8) * PS_STR + ks2 * 8 + kk];
            uint32_t a2 = Ps[(m0 + r) * PS_STR + ks2 * 8 + kk + 4];
            uint32_t a3 = Ps[(m0 + r + 8) * PS_STR + ks2 * 8 + kk + 4];
#pragma unroll
            for (int nm2 = 0; nm2 < 16; nm2++) {
                uint32_t b0 = Vs[(ks2 * 8 + kk) * VS_STR + nm2 * 8 + r];
                uint32_t b1 = Vs[(ks2 * 8 + kk + 4) * VS_STR + nm2 * 8 + r];
                MMA_TF32(oacc[nm2], a0, a1, a2, a3, b0, b1);
            }
        }
    }

    // Normalize and write out
    float li0 = 1.0f / lrow0;
    float li1 = 1.0f / lrow1;
    int row0 = qb * 128 + m0 + r;
#pragma unroll
    for (int nm2 = 0; nm2 < 16; nm2++) {
        int col = h * HD + nm2 * 8 + 2 * kk;
        *(float2*)(O + (size_t)row0 * QDIM + col) =
            make_float2(oacc[nm2][0] * li0, oacc[nm2][1] * li0);
        *(float2*)(O + (size_t)(row0 + 8) * QDIM + col) =
            make_float2(oacc[nm2][2] * li1, oacc[nm2][3] * li1);
    }
}

// ---------------------------------------------------------------------------
// Launch
// ---------------------------------------------------------------------------
extern "C" void kernel_launch(void* const* d_in, const int* in_sizes, int n_in,
                              void* d_out, int out_size)
{
    (void)in_sizes; (void)n_in; (void)out_size;

    const float* x  = (const float*)d_in[0];
    const float* wq = (const float*)d_in[1];
    const float* wk = (const float*)d_in[2];
    const float* wv = (const float*)d_in[3];
    const float* wo = (const float*)d_in[4];
    float* out = (float*)d_out;

    float *qp, *kp, *vp, *op;
    cudaGetSymbolAddress((void**)&qp, g_Q);
    cudaGetSymbolAddress((void**)&kp, g_K);
    cudaGetSymbolAddress((void**)&vp, g_V);
    cudaGetSymbolAddress((void**)&op, g_O);

    // QKV projections
    {
        dim3 gq(QDIM / 128, S_LEN / 128);
        gemm_tf32_kernel<<<gq, 256>>>(x, wq, qp, S_LEN, QDIM, D_MODEL);
        dim3 gk(KVDIM / 128, S_LEN / 128);
        gemm_tf32_kernel<<<gk, 256>>>(x, wk, kp, S_LEN, KVDIM, D_MODEL);
        gemm_tf32_kernel<<<gk, 256>>>(x, wv, vp, S_LEN, KVDIM, D_MODEL);
    }

    // RoPE
    {
        int tq = S_LEN * NH * 64;
        rope_kernel<<<(tq + 255) / 256, 256>>>(qp, NH);
        int tk = S_LEN * NKV * 64;
        rope_kernel<<<(tk + 255) / 256, 256>>>(kp, NKV);
    }

    // Attention (tensor cores)
    {
        size_t smem = (size_t)ATT_SMEM_WORDS * sizeof(uint32_t);  // ~167 KB
        cudaFuncSetAttribute(attn_mma_kernel, cudaFuncAttributeMaxDynamicSharedMemorySize, (int)smem);
        dim3 ga(S_LEN / 128, NH);
        attn_mma_kernel<<<ga, 256, smem>>>(qp, kp, vp, op);
    }

    // Output projection
    {
        dim3 go(D_MODEL / 128, S_LEN / 128);
        gemm_tf32_kernel<<<go, 256>>>(op, wo, out, S_LEN, D_MODEL, QDIM);
    }
}